// round 1
// baseline (speedup 1.0000x reference)
#include <cuda_runtime.h>
#include <cstdint>
#include <cstddef>

// Problem constants
#define B_    4
#define N_    2000
#define KN    30
#define H_    128
#define HEADS 4
#define D_    32
#define NIN   256
#define ROWS  (B_ * N_)          // 8000

// Scratch for per-head aggregated h_EV: [row][head][256] = 32.768 MB
__device__ float g_agg[(size_t)ROWS * HEADS * NIN];

// ---------------- packed fp32x2 helpers (Blackwell FFMA2) ----------------
__device__ __forceinline__ unsigned long long pack2f(float lo, float hi) {
    unsigned long long r;
    asm("mov.b64 %0, {%1, %2};" : "=l"(r) : "f"(lo), "f"(hi));
    return r;
}
__device__ __forceinline__ unsigned long long fma2(unsigned long long a,
                                                   unsigned long long b,
                                                   unsigned long long c) {
    unsigned long long d;
    asm("fma.rn.f32x2 %0, %1, %2, %3;" : "=l"(d) : "l"(a), "l"(b), "l"(c));
    return d;
}
__device__ __forceinline__ float2 unpack2f(unsigned long long v) {
    float2 f;
    asm("mov.b64 {%0, %1}, %2;" : "=f"(f.x), "=f"(f.y) : "l"(v));
    return f;
}

// =========================================================================
// Kernel 1: persistent attention + aggregation.
//   For each row (b,n):
//     Q = W_Q @ h_V  (1/32 folded in)         [smem packed weights]
//     for k: K1_i = W_K1[i,:]·h_KE[k], K2_i = W_K2[i,:]·h_KV[k]
//            (weights in REGISTERS: thread t<128 -> K1 row t; t>=128 -> K2)
//     logit[h][k] = sum_d Q*K1*K2  (warp h reduces its 32 lanes)
//     masked softmax over k, attend = softmax * mask
//     agg[h][c] = sum_k attend[h][k] * h_EV[k][c]   -> g_agg
// =========================================================================
extern "C" __global__ void __launch_bounds__(256, 1)
k1_attn(const float* __restrict__ hV,  const float* __restrict__ hEV,
        const float* __restrict__ hKV, const float* __restrict__ hKE,
        const float* __restrict__ mask,
        const float* __restrict__ WQ,  const float* __restrict__ WK1,
        const float* __restrict__ WK2)
{
    extern __shared__ float sm[];
    unsigned long long* WQt2 = (unsigned long long*)sm;   // [j2*128+i] 8192 ull = 64KB
    float* xbuf   = (float*)(WQt2 + 8192);                // 4 stages * 256 = 1024 f
    float* xv     = xbuf + 1024;                          // 128
    float* Qs     = xv + 128;                             // 128
    float* K1s    = Qs + 128;                             // 128
    float* K2s    = K1s + 128;                            // 128
    float* logits = K2s + 128;                            // 4*32 (padded)
    float* attend = logits + 128;                         // 4*32 (padded)

    const int t = threadIdx.x;

    // ---- stage W_Q packed (pairs over j): WQt2[j2*128+i] = (WQ[i,2j2], WQ[i,2j2+1])
    for (int p = t; p < 8192; p += 256) {
        int j2 = p >> 7, i = p & 127;
        WQt2[p] = pack2f(WQ[i * 128 + 2 * j2], WQ[i * 128 + 2 * j2 + 1]);
    }

    // ---- my projection-weight row into registers (packed pairs over j)
    unsigned long long wreg[64];
    {
        const float2* wsrc = (const float2*)((t < 128) ? (WK1 + t * 128)
                                                       : (WK2 + (t - 128) * 128));
        #pragma unroll
        for (int p = 0; p < 64; p++) {
            float2 w = wsrc[p];
            wreg[p] = pack2f(w.x, w.y);
        }
    }
    __syncthreads();

    const int w    = t >> 5;
    const int lane = t & 31;

    for (int row = blockIdx.x; row < ROWS; row += gridDim.x) {
        const float* ke = hKE + (size_t)row * KN * 128;
        const float* kv = hKV + (size_t)row * KN * 128;

        if (t < 128) xv[t] = hV[(size_t)row * 128 + t];
        __syncthreads();

        // ---- Q projection (threads 0..127), fold 1/D
        if (t < 128) {
            const unsigned long long* xv2 = (const unsigned long long*)xv;
            unsigned long long a0 = 0ULL, a1 = 0ULL;
            #pragma unroll
            for (int j2 = 0; j2 < 64; j2 += 2) {
                a0 = fma2(WQt2[j2 * 128 + t],       xv2[j2],     a0);
                a1 = fma2(WQt2[(j2 + 1) * 128 + t], xv2[j2 + 1], a1);
            }
            float2 fa = unpack2f(a0), fb = unpack2f(a1);
            Qs[t] = (fa.x + fa.y + fb.x + fb.y) * (1.0f / 32.0f);
        }

        // ---- preload neighbors k = 0,1 into staging ring (prefetch depth 2)
        {
            float v0 = (t < 128) ? ke[t]           : kv[t - 128];
            float v1 = (t < 128) ? ke[128 + t]     : kv[128 + t - 128];
            xbuf[0 * 256 + t] = v0;
            xbuf[1 * 256 + t] = v1;
        }
        __syncthreads();

        // ---- neighbor loop: projections + trilinear logits
        for (int k = 0; k < KN; k++) {
            float pre = 0.f;
            const bool hp = (k + 2 < KN);
            if (hp) pre = (t < 128) ? ke[(k + 2) * 128 + t]
                                    : kv[(k + 2) * 128 + (t - 128)];

            const unsigned long long* x2 = (const unsigned long long*)
                (xbuf + (k & 3) * 256 + ((t < 128) ? 0 : 128));

            unsigned long long a0 = 0ULL, a1 = 0ULL, a2 = 0ULL, a3 = 0ULL;
            #pragma unroll
            for (int p = 0; p < 64; p += 4) {
                a0 = fma2(wreg[p],     x2[p],     a0);
                a1 = fma2(wreg[p + 1], x2[p + 1], a1);
                a2 = fma2(wreg[p + 2], x2[p + 2], a2);
                a3 = fma2(wreg[p + 3], x2[p + 3], a3);
            }
            float2 f0 = unpack2f(a0), f1 = unpack2f(a1);
            float2 f2 = unpack2f(a2), f3 = unpack2f(a3);
            float dot = (f0.x + f0.y) + (f1.x + f1.y) + (f2.x + f2.y) + (f3.x + f3.y);

            if (t < 128) K1s[t] = dot; else K2s[t - 128] = dot;
            if (hp) xbuf[((k + 2) & 3) * 256 + t] = pre;
            __syncthreads();

            // trilinear: warp h reduces over its 32 lanes (i = t for t<128)
            if (t < 128) {
                float p = Qs[t] * K1s[t] * K2s[t];
                #pragma unroll
                for (int off = 16; off; off >>= 1)
                    p += __shfl_xor_sync(0xffffffffu, p, off);
                if (lane == 0) logits[w * 32 + k] = p;
            }
            __syncthreads();
        }

        // ---- masked softmax over k (warp per head)
        if (w < HEADS) {
            float m  = (lane < KN) ? mask[(size_t)row * KN + lane] : 0.f;
            float lg = (lane < KN) ? logits[w * 32 + lane] : 0.f;
            float x  = (lane < KN && m > 0.f) ? lg : -3.4028235e38f;
            float mx = x;
            #pragma unroll
            for (int off = 16; off; off >>= 1)
                mx = fmaxf(mx, __shfl_xor_sync(0xffffffffu, mx, off));
            float e = (lane < KN) ? __expf(x - mx) : 0.f;
            float s = e;
            #pragma unroll
            for (int off = 16; off; off >>= 1)
                s += __shfl_xor_sync(0xffffffffu, s, off);
            if (lane < KN) attend[w * 32 + lane] = (e / s) * m;
        }
        __syncthreads();

        // ---- aggregate h_EV: thread t handles column t (256 cols)
        {
            const float* ev = hEV + (size_t)row * KN * NIN + t;
            float a0 = 0.f, a1 = 0.f, a2 = 0.f, a3 = 0.f;
            #pragma unroll 6
            for (int k = 0; k < KN; k++) {
                float e = ev[(size_t)k * NIN];
                a0 = fmaf(attend[0 * 32 + k], e, a0);
                a1 = fmaf(attend[1 * 32 + k], e, a1);
                a2 = fmaf(attend[2 * 32 + k], e, a2);
                a3 = fmaf(attend[3 * 32 + k], e, a3);
            }
            float* ag = g_agg + (size_t)row * HEADS * NIN;
            ag[0 * NIN + t] = a0;
            ag[1 * NIN + t] = a1;
            ag[2 * NIN + t] = a2;
            ag[3 * NIN + t] = a3;
        }
        __syncthreads();
    }
}

// =========================================================================
// Kernel 2: output projection.
//   h_mid[i] = sum_c W_V[i,c] * agg[head(i), c]
//   out[o]   = sum_i W_O[o,i] * h_mid[i]
// Weights packed in smem; 2 rows per CTA iteration (256 threads).
// =========================================================================
extern "C" __global__ void __launch_bounds__(256, 1)
k2_out(const float* __restrict__ WV, const float* __restrict__ WO,
       float* __restrict__ out)
{
    extern __shared__ unsigned long long sm2[];
    unsigned long long* WVt2 = sm2;                       // 128*128 ull (pairs over c)
    unsigned long long* WOt2 = WVt2 + 128 * 128;          // 64*128 ull (pairs over i)
    float* aggs = (float*)(WOt2 + 64 * 128);              // 2 * 1024 floats
    unsigned long long* hmid2 = (unsigned long long*)(aggs + 2048); // 2*64 ull = 2*128 f

    const int t = threadIdx.x;

    for (int p = t; p < 128 * 128; p += 256) {
        int c2 = p >> 7, i = p & 127;
        WVt2[p] = pack2f(WV[i * 256 + 2 * c2], WV[i * 256 + 2 * c2 + 1]);
    }
    for (int p = t; p < 64 * 128; p += 256) {
        int i2 = p >> 7, o = p & 127;
        WOt2[p] = pack2f(WO[o * 128 + 2 * i2], WO[o * 128 + 2 * i2 + 1]);
    }
    __syncthreads();

    const int sub = t >> 7;       // which of the 2 rows this thread serves
    const int tt  = t & 127;

    for (int row0 = blockIdx.x * 2; row0 < ROWS; row0 += gridDim.x * 2) {
        const int row = row0 + sub;
        const bool valid = (row < ROWS);

        if (valid) {
            const float* ag = g_agg + (size_t)row * HEADS * NIN;
            #pragma unroll
            for (int q = 0; q < 4; q++)
                aggs[sub * 1024 + q * 256 + tt]       = ag[q * 256 + tt];
            #pragma unroll
            for (int q = 0; q < 4; q++)
                aggs[sub * 1024 + q * 256 + 128 + tt] = ag[q * 256 + 128 + tt];
        }
        __syncthreads();

        if (valid) {
            const int i = tt, h = i >> 5;
            const unsigned long long* a2 =
                (const unsigned long long*)(aggs + sub * 1024 + h * 256);
            unsigned long long acc0 = 0ULL, acc1 = 0ULL;
            #pragma unroll 8
            for (int c2 = 0; c2 < 128; c2 += 2) {
                acc0 = fma2(WVt2[c2 * 128 + i],       a2[c2],     acc0);
                acc1 = fma2(WVt2[(c2 + 1) * 128 + i], a2[c2 + 1], acc1);
            }
            float2 fa = unpack2f(acc0), fb = unpack2f(acc1);
            ((float*)hmid2)[sub * 128 + i] = fa.x + fa.y + fb.x + fb.y;
        }
        __syncthreads();

        if (valid) {
            const int o = tt;
            const unsigned long long* h2 = hmid2 + sub * 64;
            unsigned long long acc0 = 0ULL, acc1 = 0ULL;
            #pragma unroll 8
            for (int i2 = 0; i2 < 64; i2 += 2) {
                acc0 = fma2(WOt2[i2 * 128 + o],       h2[i2],     acc0);
                acc1 = fma2(WOt2[(i2 + 1) * 128 + o], h2[i2 + 1], acc1);
            }
            float2 fa = unpack2f(acc0), fb = unpack2f(acc1);
            out[(size_t)row * 128 + o] = fa.x + fa.y + fb.x + fb.y;
        }
        __syncthreads();
    }
}

// =========================================================================
extern "C" void kernel_launch(void* const* d_in, const int* in_sizes, int n_in,
                              void* d_out, int out_size)
{
    (void)in_sizes; (void)n_in; (void)out_size;
    const float* hV   = (const float*)d_in[0];
    const float* hEV  = (const float*)d_in[1];
    const float* hKV  = (const float*)d_in[2];
    const float* hKE  = (const float*)d_in[3];
    const float* mask = (const float*)d_in[4];
    const float* WQ   = (const float*)d_in[5];
    const float* WK1  = (const float*)d_in[6];
    const float* WK2  = (const float*)d_in[7];
    const float* WV   = (const float*)d_in[8];
    const float* WO   = (const float*)d_in[9];
    float* out = (float*)d_out;

    // smem budgets
    const int smem1 = (8192 * 8) + (1024 + 128 * 4 + 256) * 4;   // ~71 KB
    const int smem2 = 128 * 128 * 8 + 64 * 128 * 8 + 2048 * 4 + 128 * 8; // ~201 KB

    cudaFuncSetAttribute(k1_attn, cudaFuncAttributeMaxDynamicSharedMemorySize, smem1);
    cudaFuncSetAttribute(k2_out,  cudaFuncAttributeMaxDynamicSharedMemorySize, smem2);

    k1_attn<<<152, 256, smem1>>>(hV, hEV, hKV, hKE, mask, WQ, WK1, WK2);
    k2_out<<<152, 256, smem2>>>(WV, WO, out);
}

// round 5
// speedup vs baseline: 2.2294x; 2.2294x over previous
#include <cuda_runtime.h>
#include <cstdint>
#include <cstddef>

#define KN     30
#define ROWS   8000
#define GRID   152
#define NEG_INF_F (-3.402823466e38f)

// ---------------- packed fp32x2 helpers (Blackwell FFMA2) ----------------
__device__ __forceinline__ unsigned long long pack2f(float lo, float hi) {
    unsigned long long r;
    asm("mov.b64 %0, {%1, %2};" : "=l"(r) : "f"(lo), "f"(hi));
    return r;
}
__device__ __forceinline__ unsigned long long fma2(unsigned long long a,
                                                   unsigned long long b,
                                                   unsigned long long c) {
    unsigned long long d;
    asm("fma.rn.f32x2 %0, %1, %2, %3;" : "=l"(d) : "l"(a), "l"(b), "l"(c));
    return d;
}
__device__ __forceinline__ float hsum2(unsigned long long v) {
    float lo, hi;
    asm("mov.b64 {%0, %1}, %2;" : "=f"(lo), "=f"(hi) : "l"(v));
    return lo + hi;
}

// Shared float-offset layout (49696 floats = 198784 B)
#define OFF_XBUF 32768            // 7808 floats: ke 3840 | kv 3840 | xv 128
#define OFF_MASK (OFF_XBUF + 7808)  // 32
#define OFF_K1S  (OFF_MASK + 32)    // 3840
#define OFF_K2S  (OFF_K1S + 3840)   // 3840
#define OFF_AGG  (OFF_K2S + 3840)   // 1024
#define OFF_HMID (OFF_AGG + 1024)   // 128
#define OFF_LG   (OFF_HMID + 128)   // 128
#define OFF_AT   (OFF_LG + 128)     // 128
#define SMEM_FLOATS (OFF_AT + 128)

extern "C" __global__ void __launch_bounds__(256, 1)
fused_attn(const float* __restrict__ hV,  const float* __restrict__ hEV,
           const float* __restrict__ hKV, const float* __restrict__ hKE,
           const float* __restrict__ mask,
           const float* __restrict__ WQ,  const float* __restrict__ WK1,
           const float* __restrict__ WK2, const float* __restrict__ WV,
           const float* __restrict__ WO,  float* __restrict__ out)
{
    extern __shared__ float sm[];
    unsigned long long* WVp = (unsigned long long*)sm;  // 16384 ull
    float* xbuf   = sm + OFF_XBUF;
    float* smask  = sm + OFF_MASK;
    float* K1s    = sm + OFF_K1S;
    float* K2s    = sm + OFF_K2S;
    float* agg    = sm + OFF_AGG;
    float* hmid   = sm + OFF_HMID;
    float* lg_t   = sm + OFF_LG;
    float* at_t   = sm + OFF_AT;

    const int t    = threadIdx.x;
    const int w5   = t >> 5;
    const int lane = t & 31;
    const bool isK1 = (t < 128);
    const int u = t & 127;

    // ---- stage W_V packed into smem once (persistent CTA) ----
    {
        const float2* wv2 = (const float2*)WV;   // 128 float2 per row
        for (int p = t; p < 16384; p += 256) {
            int c2 = p >> 7, i = p & 127;
            float2 v = wv2[i * 128 + c2];
            WVp[p] = pack2f(v.x, v.y);
        }
    }

    // ---- my K-projection weight row into registers (64 packed pairs) ----
    unsigned long long wreg[64];
    {
        const float2* wsrc = (const float2*)(isK1 ? (WK1 + u * 128)
                                                  : (WK2 + u * 128));
        #pragma unroll
        for (int p = 0; p < 64; p++) {
            float2 v = wsrc[p];
            wreg[p] = pack2f(v.x, v.y);
        }
    }
    __syncthreads();

    for (int row = blockIdx.x; row < ROWS; row += GRID) {
        // ================= stage current row (plain loads, MLP=8) =========
        {
            const float4* gke = (const float4*)(hKE + (size_t)row * (KN * 128));
            const float4* gkv = (const float4*)(hKV + (size_t)row * (KN * 128));
            const float4* gxv = (const float4*)(hV  + (size_t)row * 128);
            float4 v[8];
            float mv = 0.f;
            #pragma unroll
            for (int s = 0; s < 8; s++) {
                int q = t + 256 * s;           // 0..2047, need 0..1951
                if (q < 960)        v[s] = gke[q];
                else if (q < 1920)  v[s] = gkv[q - 960];
                else if (q < 1952)  v[s] = gxv[q - 1920];
            }
            if (t < KN) mv = mask[(size_t)row * KN + t];
            float4* s4 = (float4*)xbuf;
            #pragma unroll
            for (int s = 0; s < 8; s++) {
                int q = t + 256 * s;
                if (q < 1952) s4[q] = v[s];
            }
            if (t < KN) smask[t] = mv;
        }
        __syncthreads();

        // ================= Q projection (t<128), fold 1/32 ================
        float Qv = 0.f;
        if (isK1) {
            const float4* wq4 = (const float4*)(WQ + u * 128);
            const float4* xv4 = (const float4*)(xbuf + 7680);
            float q0 = 0.f, q1 = 0.f, q2 = 0.f, q3 = 0.f;
            #pragma unroll
            for (int p = 0; p < 32; p++) {
                float4 wv = wq4[p], xvv = xv4[p];
                q0 = fmaf(wv.x, xvv.x, q0);
                q1 = fmaf(wv.y, xvv.y, q1);
                q2 = fmaf(wv.z, xvv.z, q2);
                q3 = fmaf(wv.w, xvv.w, q3);
            }
            Qv = (q0 + q1 + q2 + q3) * (1.0f / 32.0f);
        }

        // ================= 30 barrier-free 128-dim dots ===================
        {
            const float* xs = xbuf + (isK1 ? 0 : 3840);
            float* dst = isK1 ? K1s : K2s;
            #pragma unroll 2
            for (int k = 0; k < KN; k++) {
                const unsigned long long* x2 =
                    (const unsigned long long*)(xs + k * 128);
                unsigned long long a0 = 0, a1 = 0, a2 = 0, a3 = 0;
                #pragma unroll
                for (int p = 0; p < 64; p += 4) {
                    a0 = fma2(wreg[p],     x2[p],     a0);
                    a1 = fma2(wreg[p + 1], x2[p + 1], a1);
                    a2 = fma2(wreg[p + 2], x2[p + 2], a2);
                    a3 = fma2(wreg[p + 3], x2[p + 3], a3);
                }
                dst[k * 128 + u] = (hsum2(a0) + hsum2(a1)) + (hsum2(a2) + hsum2(a3));
            }
        }
        __syncthreads();

        // ================= trilinear logits (warps 0-3) ===================
        if (isK1) {
            #pragma unroll
            for (int k = 0; k < KN; k++) {
                float p = Qv * K1s[k * 128 + t] * K2s[k * 128 + t];
                #pragma unroll
                for (int off = 16; off; off >>= 1)
                    p += __shfl_xor_sync(0xffffffffu, p, off);
                if (lane == 0) lg_t[k * 4 + w5] = p;
            }
        }
        __syncthreads();

        // ================= masked softmax (warp per head) =================
        if (isK1) {
            float m_ = 0.f, x = NEG_INF_F;
            if (lane < KN) {
                m_ = smask[lane];
                if (m_ > 0.f) x = lg_t[lane * 4 + w5];
            }
            float mx = x;
            #pragma unroll
            for (int off = 16; off; off >>= 1)
                mx = fmaxf(mx, __shfl_xor_sync(0xffffffffu, mx, off));
            float e = (lane < KN) ? __expf(x - mx) : 0.f;
            float s = e;
            #pragma unroll
            for (int off = 16; off; off >>= 1)
                s += __shfl_xor_sync(0xffffffffu, s, off);
            if (lane < KN) at_t[lane * 4 + w5] = (e / s) * m_;
        }
        __syncthreads();

        // ================= aggregate h_EV (thread t = column t) ===========
        {
            const float* ev = hEV + (size_t)row * (KN * 256) + t;
            float b0 = 0.f, b1 = 0.f, b2 = 0.f, b3 = 0.f;
            #pragma unroll 6
            for (int k = 0; k < KN; k++) {
                float e = ev[(size_t)k * 256];
                float4 at = *(const float4*)(at_t + 4 * k);
                b0 = fmaf(at.x, e, b0);
                b1 = fmaf(at.y, e, b1);
                b2 = fmaf(at.z, e, b2);
                b3 = fmaf(at.w, e, b3);
            }
            agg[t]       = b0;
            agg[256 + t] = b1;
            agg[512 + t] = b2;
            agg[768 + t] = b3;
        }
        __syncthreads();

        // ================= V projection: hmid[i], i = t < 128 =============
        if (isK1) {
            const int h = t >> 5;
            const unsigned long long* a2 =
                (const unsigned long long*)(agg + h * 256);
            unsigned long long c0 = 0, c1 = 0, c2a = 0, c3 = 0;
            #pragma unroll
            for (int j2 = 0; j2 < 128; j2 += 4) {
                c0  = fma2(WVp[j2       * 128 + t], a2[j2],     c0);
                c1  = fma2(WVp[(j2 + 1) * 128 + t], a2[j2 + 1], c1);
                c2a = fma2(WVp[(j2 + 2) * 128 + t], a2[j2 + 2], c2a);
                c3  = fma2(WVp[(j2 + 3) * 128 + t], a2[j2 + 3], c3);
            }
            hmid[t] = (hsum2(c0) + hsum2(c1)) + (hsum2(c2a) + hsum2(c3));
        }
        __syncthreads();

        // ================= O projection: out[o], o = t-128 ================
        if (!isK1) {
            const float4* wo4 = (const float4*)(WO + u * 128);
            const float4* hm4 = (const float4*)hmid;
            float q0 = 0.f, q1 = 0.f, q2 = 0.f, q3 = 0.f;
            #pragma unroll
            for (int p = 0; p < 32; p++) {
                float4 wv = wo4[p], hv = hm4[p];
                q0 = fmaf(wv.x, hv.x, q0);
                q1 = fmaf(wv.y, hv.y, q1);
                q2 = fmaf(wv.z, hv.z, q2);
                q3 = fmaf(wv.w, hv.w, q3);
            }
            out[(size_t)row * 128 + u] = (q0 + q1) + (q2 + q3);
        }
        __syncthreads();   // protect xbuf/smask/hmid before next staging
    }
}

// =========================================================================
extern "C" void kernel_launch(void* const* d_in, const int* in_sizes, int n_in,
                              void* d_out, int out_size)
{
    (void)in_sizes; (void)n_in; (void)out_size;
    const float* hV   = (const float*)d_in[0];
    const float* hEV  = (const float*)d_in[1];
    const float* hKV  = (const float*)d_in[2];
    const float* hKE  = (const float*)d_in[3];
    const float* mask = (const float*)d_in[4];
    const float* WQ   = (const float*)d_in[5];
    const float* WK1  = (const float*)d_in[6];
    const float* WK2  = (const float*)d_in[7];
    const float* WV   = (const float*)d_in[8];
    const float* WO   = (const float*)d_in[9];
    float* out = (float*)d_out;

    const int smem = SMEM_FLOATS * 4;   // 198784 B
    cudaFuncSetAttribute(fused_attn, cudaFuncAttributeMaxDynamicSharedMemorySize, smem);
    fused_attn<<<GRID, 256, smem>>>(hV, hEV, hKV, hKE, mask,
                                    WQ, WK1, WK2, WV, WO, out);
}